// round 5
// baseline (speedup 1.0000x reference)
#include <cuda_runtime.h>
#include <cuda_bf16.h>
#include <cstdint>

// ---------------- problem constants ----------------
#define N_NODES   100000
#define N_EDGES   1600000
#define NUM_GRAPHS 1024
#define IN_FEAT   7
#define H         128
#define BN_EPS    1e-5f

#define LDP 132   // padded smem row stride (floats): 16B-aligned, kills bank conflicts

// ---------------- scratch (device globals, no allocation) ----------------
__device__ __align__(256) float g_agg[(size_t)N_NODES * H];     // also N x 8 for layer 0
__device__ __align__(256) float g_cat[(size_t)N_NODES * 3 * H];
__device__ __align__(256) float g_pool[(size_t)NUM_GRAPHS * 3 * H];
__device__ __align__(256) float g_hid[(size_t)NUM_GRAPHS * 2 * H];

// ---------------- helpers ----------------
__device__ __forceinline__ void red_add_v4(float* addr, float4 v) {
    asm volatile("red.global.add.v4.f32 [%0], {%1, %2, %3, %4};"
                 :: "l"(addr), "f"(v.x), "f"(v.y), "f"(v.z), "f"(v.w)
                 : "memory");
}

// ---------------- layer 0: scatter of 7-dim raw features ----------------
__global__ void scatter7_kernel(const float* __restrict__ x,
                                const int* __restrict__ src,
                                const int* __restrict__ dst,
                                float* __restrict__ agg, int E)
{
    int e = blockIdx.x * blockDim.x + threadIdx.x;
    if (e >= E) return;
    int s = src[e];
    int d = dst[e];
    const float* xr = x + (size_t)s * IN_FEAT;
    float* ar = agg + (size_t)d * 8;
    #pragma unroll
    for (int k = 0; k < IN_FEAT; k++) atomicAdd(ar + k, xr[k]);
}

// ---------------- scatter for H=128 features: 4 edges per warp ----------------
__global__ void scatter128_kernel(const float* __restrict__ h, int ldH,
                                  const int* __restrict__ src,
                                  const int* __restrict__ dst,
                                  float* __restrict__ agg, int E)
{
    int warp = (blockIdx.x * blockDim.x + threadIdx.x) >> 5;
    int lane = threadIdx.x & 31;
    int e0 = warp * 4;
    if (e0 >= E) return;

    int s[4], d[4];
    #pragma unroll
    for (int i = 0; i < 4; i++) {
        int e = (e0 + i < E) ? (e0 + i) : (E - 1);
        s[i] = __ldg(src + e);
        d[i] = __ldg(dst + e);
    }
    float4 v[4];
    #pragma unroll
    for (int i = 0; i < 4; i++)
        v[i] = *reinterpret_cast<const float4*>(h + (size_t)s[i] * ldH + lane * 4);
    #pragma unroll
    for (int i = 0; i < 4; i++)
        if (e0 + i < E)
            red_add_v4(agg + (size_t)d[i] * H + lane * 4, v[i]);
}

// ---------------- fused GIN MLP (layers 1,2) ----------------
// C = relu(relu((A1+A2)@B1+b1)@B2+b2)
// smem: z_s[128*LDP] | As[16*LDP] | Bs[16*LDP]
__global__ void __launch_bounds__(256, 2)
fused_mlp_kernel(const float* __restrict__ A1, int ldA,
                 const float* __restrict__ A2,
                 const float* __restrict__ B1, const float* __restrict__ b1,
                 const float* __restrict__ B2, const float* __restrict__ b2,
                 float* __restrict__ C, int ldC, int N)
{
    extern __shared__ float sm[];
    float* z_s = sm;                      // 128 x LDP
    float* As  = sm + 128 * LDP;          // 16 x LDP (k-major)
    float* Bs  = As + 16 * LDP;           // 16 x LDP

    int tid = threadIdx.x;
    int tx = tid & 15, ty = tid >> 4;
    int m0 = blockIdx.x * 128;

    float acc[8][8];
    #pragma unroll
    for (int i = 0; i < 8; i++)
        #pragma unroll
        for (int j = 0; j < 8; j++) acc[i][j] = 0.f;

    // ---- phase 1: z = relu((A1+A2) @ B1 + b1) ----
    for (int kt = 0; kt < H; kt += 16) {
        #pragma unroll
        for (int u = 0; u < 2; u++) {
            int i = tid + u * 256;
            int row = i >> 2;
            int c4 = (i & 3) * 4;
            float4 v = make_float4(0.f, 0.f, 0.f, 0.f);
            int gr = m0 + row;
            if (gr < N) {
                v = *reinterpret_cast<const float4*>(A1 + (size_t)gr * ldA + kt + c4);
                float4 w = *reinterpret_cast<const float4*>(A2 + (size_t)gr * H + kt + c4);
                v.x += w.x; v.y += w.y; v.z += w.z; v.w += w.w;
            }
            As[(c4 + 0) * LDP + row] = v.x;
            As[(c4 + 1) * LDP + row] = v.y;
            As[(c4 + 2) * LDP + row] = v.z;
            As[(c4 + 3) * LDP + row] = v.w;
        }
        #pragma unroll
        for (int u = 0; u < 2; u++) {
            int i = tid + u * 256;
            int kr = i >> 5;
            int c4 = (i & 31) * 4;
            *reinterpret_cast<float4*>(&Bs[kr * LDP + c4]) =
                *reinterpret_cast<const float4*>(B1 + (size_t)(kt + kr) * H + c4);
        }
        __syncthreads();
        #pragma unroll
        for (int k = 0; k < 16; k++) {
            float4 a0 = *reinterpret_cast<const float4*>(&As[k * LDP + ty * 8]);
            float4 a1 = *reinterpret_cast<const float4*>(&As[k * LDP + ty * 8 + 4]);
            float4 b0 = *reinterpret_cast<const float4*>(&Bs[k * LDP + tx * 8]);
            float4 b1v = *reinterpret_cast<const float4*>(&Bs[k * LDP + tx * 8 + 4]);
            float ra[8] = {a0.x, a0.y, a0.z, a0.w, a1.x, a1.y, a1.z, a1.w};
            float rb[8] = {b0.x, b0.y, b0.z, b0.w, b1v.x, b1v.y, b1v.z, b1v.w};
            #pragma unroll
            for (int i = 0; i < 8; i++)
                #pragma unroll
                for (int j = 0; j < 8; j++) acc[i][j] += ra[i] * rb[j];
        }
        __syncthreads();
    }

    // epilogue 1: bias + relu -> z_s
    #pragma unroll
    for (int i = 0; i < 8; i++) {
        int r = ty * 8 + i;
        #pragma unroll
        for (int j4 = 0; j4 < 2; j4++) {
            int j0 = tx * 8 + j4 * 4;
            float4 o;
            o.x = fmaxf(acc[i][j4 * 4 + 0] + b1[j0 + 0], 0.f);
            o.y = fmaxf(acc[i][j4 * 4 + 1] + b1[j0 + 1], 0.f);
            o.z = fmaxf(acc[i][j4 * 4 + 2] + b1[j0 + 2], 0.f);
            o.w = fmaxf(acc[i][j4 * 4 + 3] + b1[j0 + 3], 0.f);
            *reinterpret_cast<float4*>(&z_s[r * LDP + j0]) = o;
        }
    }

    // ---- phase 2: C = relu(z @ B2 + b2) ----
    float acc2[8][8];
    #pragma unroll
    for (int i = 0; i < 8; i++)
        #pragma unroll
        for (int j = 0; j < 8; j++) acc2[i][j] = 0.f;

    for (int kt = 0; kt < H; kt += 16) {
        #pragma unroll
        for (int u = 0; u < 2; u++) {
            int i = tid + u * 256;
            int kr = i >> 5;
            int c4 = (i & 31) * 4;
            *reinterpret_cast<float4*>(&Bs[kr * LDP + c4]) =
                *reinterpret_cast<const float4*>(B2 + (size_t)(kt + kr) * H + c4);
        }
        __syncthreads();
        #pragma unroll
        for (int k = 0; k < 16; k++) {
            float4 b0 = *reinterpret_cast<const float4*>(&Bs[k * LDP + tx * 8]);
            float4 b1v = *reinterpret_cast<const float4*>(&Bs[k * LDP + tx * 8 + 4]);
            float rb[8] = {b0.x, b0.y, b0.z, b0.w, b1v.x, b1v.y, b1v.z, b1v.w};
            float ra[8];
            #pragma unroll
            for (int i = 0; i < 8; i++) ra[i] = z_s[(ty * 8 + i) * LDP + kt + k];
            #pragma unroll
            for (int i = 0; i < 8; i++)
                #pragma unroll
                for (int j = 0; j < 8; j++) acc2[i][j] += ra[i] * rb[j];
        }
        __syncthreads();
    }

    // epilogue 2: bias + relu -> C
    #pragma unroll
    for (int i = 0; i < 8; i++) {
        int gr = m0 + ty * 8 + i;
        if (gr < N) {
            #pragma unroll
            for (int j4 = 0; j4 < 2; j4++) {
                int j0 = tx * 8 + j4 * 4;
                float4 o;
                o.x = fmaxf(acc2[i][j4 * 4 + 0] + b2[j0 + 0], 0.f);
                o.y = fmaxf(acc2[i][j4 * 4 + 1] + b2[j0 + 1], 0.f);
                o.z = fmaxf(acc2[i][j4 * 4 + 2] + b2[j0 + 2], 0.f);
                o.w = fmaxf(acc2[i][j4 * 4 + 3] + b2[j0 + 3], 0.f);
                *reinterpret_cast<float4*>(C + (size_t)gr * ldC + j0) = o;
            }
        }
    }
}

// ---------------- fused layer-0 MLP: K1 = 7 ----------------
// smem: z_s[128*LDP] | in_s[128*8] | Bs[16*LDP]
__global__ void __launch_bounds__(256, 2)
fused_l0_kernel(const float* __restrict__ x,
                const float* __restrict__ agg7,
                const float* __restrict__ B1, const float* __restrict__ b1,
                const float* __restrict__ B2, const float* __restrict__ b2,
                float* __restrict__ C, int ldC, int N)
{
    extern __shared__ float sm[];
    float* z_s  = sm;                     // 128 x LDP
    float* in_s = sm + 128 * LDP;         // 128 x 8
    float* Bs   = in_s + 1024;            // 16 x LDP

    int tid = threadIdx.x;
    int tx = tid & 15, ty = tid >> 4;
    int m0 = blockIdx.x * 128;

    for (int i = tid; i < 128 * IN_FEAT; i += 256) {
        int r = i / IN_FEAT, k = i % IN_FEAT;
        int gr = m0 + r;
        in_s[r * 8 + k] = (gr < N)
            ? x[(size_t)gr * IN_FEAT + k] + agg7[(size_t)gr * 8 + k] : 0.f;
    }
    for (int i = tid; i < IN_FEAT * H; i += 256) {
        int kr = i >> 7, c = i & 127;
        Bs[kr * LDP + c] = B1[i];
    }
    __syncthreads();

    // phase 1: z = relu(in @ B1 + b1)
    float acc[8][8];
    #pragma unroll
    for (int i = 0; i < 8; i++)
        #pragma unroll
        for (int j = 0; j < 8; j++) acc[i][j] = 0.f;

    #pragma unroll
    for (int k = 0; k < IN_FEAT; k++) {
        float4 b0 = *reinterpret_cast<const float4*>(&Bs[k * LDP + tx * 8]);
        float4 b1v = *reinterpret_cast<const float4*>(&Bs[k * LDP + tx * 8 + 4]);
        float rb[8] = {b0.x, b0.y, b0.z, b0.w, b1v.x, b1v.y, b1v.z, b1v.w};
        float ra[8];
        #pragma unroll
        for (int i = 0; i < 8; i++) ra[i] = in_s[(ty * 8 + i) * 8 + k];
        #pragma unroll
        for (int i = 0; i < 8; i++)
            #pragma unroll
            for (int j = 0; j < 8; j++) acc[i][j] += ra[i] * rb[j];
    }

    #pragma unroll
    for (int i = 0; i < 8; i++) {
        int r = ty * 8 + i;
        #pragma unroll
        for (int j4 = 0; j4 < 2; j4++) {
            int j0 = tx * 8 + j4 * 4;
            float4 o;
            o.x = fmaxf(acc[i][j4 * 4 + 0] + b1[j0 + 0], 0.f);
            o.y = fmaxf(acc[i][j4 * 4 + 1] + b1[j0 + 1], 0.f);
            o.z = fmaxf(acc[i][j4 * 4 + 2] + b1[j0 + 2], 0.f);
            o.w = fmaxf(acc[i][j4 * 4 + 3] + b1[j0 + 3], 0.f);
            *reinterpret_cast<float4*>(&z_s[r * LDP + j0]) = o;
        }
    }
    __syncthreads();   // B1 reads done before Bs overwrite

    // phase 2: C = relu(z @ B2 + b2)
    float acc2[8][8];
    #pragma unroll
    for (int i = 0; i < 8; i++)
        #pragma unroll
        for (int j = 0; j < 8; j++) acc2[i][j] = 0.f;

    for (int kt = 0; kt < H; kt += 16) {
        #pragma unroll
        for (int u = 0; u < 2; u++) {
            int i = tid + u * 256;
            int kr = i >> 5;
            int c4 = (i & 31) * 4;
            *reinterpret_cast<float4*>(&Bs[kr * LDP + c4]) =
                *reinterpret_cast<const float4*>(B2 + (size_t)(kt + kr) * H + c4);
        }
        __syncthreads();
        #pragma unroll
        for (int k = 0; k < 16; k++) {
            float4 b0 = *reinterpret_cast<const float4*>(&Bs[k * LDP + tx * 8]);
            float4 b1v = *reinterpret_cast<const float4*>(&Bs[k * LDP + tx * 8 + 4]);
            float rb[8] = {b0.x, b0.y, b0.z, b0.w, b1v.x, b1v.y, b1v.z, b1v.w};
            float ra[8];
            #pragma unroll
            for (int i = 0; i < 8; i++) ra[i] = z_s[(ty * 8 + i) * LDP + kt + k];
            #pragma unroll
            for (int i = 0; i < 8; i++)
                #pragma unroll
                for (int j = 0; j < 8; j++) acc2[i][j] += ra[i] * rb[j];
        }
        __syncthreads();
    }

    #pragma unroll
    for (int i = 0; i < 8; i++) {
        int gr = m0 + ty * 8 + i;
        if (gr < N) {
            #pragma unroll
            for (int j4 = 0; j4 < 2; j4++) {
                int j0 = tx * 8 + j4 * 4;
                float4 o;
                o.x = fmaxf(acc2[i][j4 * 4 + 0] + b2[j0 + 0], 0.f);
                o.y = fmaxf(acc2[i][j4 * 4 + 1] + b2[j0 + 1], 0.f);
                o.z = fmaxf(acc2[i][j4 * 4 + 2] + b2[j0 + 2], 0.f);
                o.w = fmaxf(acc2[i][j4 * 4 + 3] + b2[j0 + 3], 0.f);
                *reinterpret_cast<float4*>(C + (size_t)gr * ldC + j0) = o;
            }
        }
    }
}

// ---------------- global add pool over batch ids ----------------
__global__ void pool_kernel(const float* __restrict__ cat,
                            const int* __restrict__ batch,
                            float* __restrict__ pool, int N)
{
    int t = blockIdx.x * blockDim.x + threadIdx.x;
    int total = N * 96;
    if (t >= total) return;
    int n = t / 96;
    int q = t % 96;
    int g = batch[n];
    float4 v = reinterpret_cast<const float4*>(cat)[(size_t)n * 96 + q];
    red_add_v4(pool + (size_t)g * 384 + q * 4, v);
}

// ---------------- classifier layer 1: 16 graphs/block, 384 -> 256 + BN + relu --
__global__ void clf1_kernel(const float* __restrict__ pool,
                            const float* __restrict__ w,
                            const float* __restrict__ b,
                            const float* __restrict__ gamma,
                            const float* __restrict__ beta,
                            const float* __restrict__ mean,
                            const float* __restrict__ var,
                            float* __restrict__ hid)
{
    __shared__ float sp[16 * 384];
    int g0 = blockIdx.x * 16;
    int j = threadIdx.x;                 // 256
    for (int i = j; i < 16 * 384; i += 256)
        sp[i] = pool[(size_t)g0 * 384 + i];
    __syncthreads();

    float acc[16];
    float bj = b[j];
    #pragma unroll
    for (int g = 0; g < 16; g++) acc[g] = bj;

    for (int k = 0; k < 384; k++) {
        float wv = __ldg(w + (size_t)k * 256 + j);
        #pragma unroll
        for (int g = 0; g < 16; g++) acc[g] += sp[g * 384 + k] * wv;
    }

    float scale = rsqrtf(var[j] + BN_EPS) * gamma[j];
    float shift = beta[j] - mean[j] * scale;
    #pragma unroll
    for (int g = 0; g < 16; g++)
        hid[(size_t)(g0 + g) * 256 + j] = fmaxf(acc[g] * scale + shift, 0.f);
}

// ---------------- classifier layer 2: 256 -> 2 ----------------
__global__ void clf2_kernel(const float* __restrict__ hid,
                            const float* __restrict__ w,
                            const float* __restrict__ b,
                            float* __restrict__ out)
{
    int t = blockIdx.x * blockDim.x + threadIdx.x;
    if (t >= NUM_GRAPHS * 2) return;
    int g = t >> 1, j = t & 1;
    float acc = b[j];
    const float* hr = hid + (size_t)g * 256;
    #pragma unroll 8
    for (int k = 0; k < 256; k++) acc += hr[k] * __ldg(w + k * 2 + j);
    out[t] = acc;
}

// ---------------- launch ----------------
extern "C" void kernel_launch(void* const* d_in, const int* in_sizes, int n_in,
                              void* d_out, int out_size)
{
    const float* x      = (const float*)d_in[0];
    const int*   ei     = (const int*)d_in[1];
    const int*   batch  = (const int*)d_in[2];
    const float* w1[3], *b1[3], *w2[3], *b2[3];
    for (int l = 0; l < 3; l++) {
        w1[l] = (const float*)d_in[3 + 4 * l + 0];
        b1[l] = (const float*)d_in[3 + 4 * l + 1];
        w2[l] = (const float*)d_in[3 + 4 * l + 2];
        b2[l] = (const float*)d_in[3 + 4 * l + 3];
    }
    const float* clf_w1 = (const float*)d_in[15];
    const float* clf_b1 = (const float*)d_in[16];
    const float* clf_w2 = (const float*)d_in[17];
    const float* clf_b2 = (const float*)d_in[18];
    const float* bn_g   = (const float*)d_in[19];
    const float* bn_b   = (const float*)d_in[20];
    const float* bn_m   = (const float*)d_in[21];
    const float* bn_v   = (const float*)d_in[22];
    float* out = (float*)d_out;

    const int N = in_sizes[0] / IN_FEAT;     // 100000
    const int E = in_sizes[1] / 2;           // 1600000

    float *d_agg, *d_cat, *d_pool, *d_hid;
    cudaGetSymbolAddress((void**)&d_agg, g_agg);
    cudaGetSymbolAddress((void**)&d_cat, g_cat);
    cudaGetSymbolAddress((void**)&d_pool, g_pool);
    cudaGetSymbolAddress((void**)&d_hid, g_hid);

    const int* src = ei;
    const int* dst = ei + E;

    const int gemm_blocks = (N + 127) / 128;
    const int SMEM_MLP = (128 * LDP + 16 * LDP + 16 * LDP) * 4;   // 84480
    const int SMEM_L0  = (128 * LDP + 1024 + 16 * LDP) * 4;       // 80128
    cudaFuncSetAttribute(fused_mlp_kernel, cudaFuncAttributeMaxDynamicSharedMemorySize, SMEM_MLP);
    cudaFuncSetAttribute(fused_l0_kernel,  cudaFuncAttributeMaxDynamicSharedMemorySize, SMEM_L0);

    // ---- layer 0 ----
    cudaMemsetAsync(d_agg, 0, (size_t)N * 8 * sizeof(float));
    scatter7_kernel<<<(E + 255) / 256, 256>>>(x, src, dst, d_agg, E);
    fused_l0_kernel<<<gemm_blocks, 256, SMEM_L0>>>(x, d_agg, w1[0], b1[0],
                                                   w2[0], b2[0], d_cat, 3 * H, N);

    // ---- layers 1, 2 ----
    for (int l = 1; l < 3; l++) {
        const float* h_prev = d_cat + (size_t)(l - 1) * H;  // row stride 384
        cudaMemsetAsync(d_agg, 0, (size_t)N * H * sizeof(float));
        int warps = (E + 3) / 4;
        scatter128_kernel<<<(warps * 32 + 255) / 256, 256>>>(h_prev, 3 * H, src, dst, d_agg, E);
        fused_mlp_kernel<<<gemm_blocks, 256, SMEM_MLP>>>(h_prev, 3 * H, d_agg,
                                                         w1[l], b1[l], w2[l], b2[l],
                                                         d_cat + (size_t)l * H, 3 * H, N);
    }

    // ---- global add pool ----
    cudaMemsetAsync(d_pool, 0, (size_t)NUM_GRAPHS * 384 * sizeof(float));
    pool_kernel<<<(N * 96 + 255) / 256, 256>>>(d_cat, batch, d_pool, N);

    // ---- classifier ----
    clf1_kernel<<<NUM_GRAPHS / 16, 256>>>(d_pool, clf_w1, clf_b1, bn_g, bn_b, bn_m, bn_v, d_hid);
    clf2_kernel<<<(NUM_GRAPHS * 2 + 255) / 256, 256>>>(d_hid, clf_w2, clf_b2, out);
}

// round 6
// speedup vs baseline: 1.0603x; 1.0603x over previous
#include <cuda_runtime.h>
#include <cuda_bf16.h>
#include <cstdint>

// ---------------- problem constants ----------------
#define N_NODES   100000
#define N_EDGES   1600000
#define NUM_GRAPHS 1024
#define IN_FEAT   7
#define H         128
#define BN_EPS    1e-5f

#define LDP 132   // padded smem row stride (floats)

typedef unsigned long long ull;

// ---------------- scratch (device globals, no allocation) ----------------
__device__ __align__(256) float g_agg[(size_t)N_NODES * H];     // also N x 8 for layer 0
__device__ __align__(256) float g_cat[(size_t)N_NODES * 3 * H];
__device__ __align__(256) float g_pool[(size_t)NUM_GRAPHS * 3 * H];
__device__ __align__(256) float g_hid[(size_t)NUM_GRAPHS * 2 * H];

// ---------------- f32x2 packed-math helpers ----------------
__device__ __forceinline__ void ffma2(ull& d, ull a, ull b) {
    asm("fma.rn.f32x2 %0, %1, %2, %0;" : "+l"(d) : "l"(a), "l"(b));
}
__device__ __forceinline__ ull pkdup(float a) {
    ull r; asm("mov.b64 %0, {%1, %1};" : "=l"(r) : "f"(a)); return r;
}
__device__ __forceinline__ float2 unpk(ull v) {
    float2 r; asm("mov.b64 {%0, %1}, %2;" : "=f"(r.x), "=f"(r.y) : "l"(v)); return r;
}
__device__ __forceinline__ void red_add_v4(float* addr, float4 v) {
    asm volatile("red.global.add.v4.f32 [%0], {%1, %2, %3, %4};"
                 :: "l"(addr), "f"(v.x), "f"(v.y), "f"(v.z), "f"(v.w)
                 : "memory");
}
__device__ __forceinline__ float f4c(const float4& v, int k) {
    return (k == 0) ? v.x : (k == 1) ? v.y : (k == 2) ? v.z : v.w;
}

// ---------------- layer 0: scatter of 7-dim raw features ----------------
__global__ void scatter7_kernel(const float* __restrict__ x,
                                const int* __restrict__ src,
                                const int* __restrict__ dst,
                                float* __restrict__ agg, int E)
{
    int e = blockIdx.x * blockDim.x + threadIdx.x;
    if (e >= E) return;
    int s = src[e];
    int d = dst[e];
    const float* xr = x + (size_t)s * IN_FEAT;
    float* ar = agg + (size_t)d * 8;
    #pragma unroll
    for (int k = 0; k < IN_FEAT; k++) atomicAdd(ar + k, xr[k]);
}

// ---------------- scatter for H=128 features: 4 edges per warp ----------------
__global__ void scatter128_kernel(const float* __restrict__ h, int ldH,
                                  const int* __restrict__ src,
                                  const int* __restrict__ dst,
                                  float* __restrict__ agg, int E)
{
    int warp = (blockIdx.x * blockDim.x + threadIdx.x) >> 5;
    int lane = threadIdx.x & 31;
    int e0 = warp * 4;
    if (e0 >= E) return;

    int s[4], d[4];
    #pragma unroll
    for (int i = 0; i < 4; i++) {
        int e = (e0 + i < E) ? (e0 + i) : (E - 1);
        s[i] = __ldg(src + e);
        d[i] = __ldg(dst + e);
    }
    float4 v[4];
    #pragma unroll
    for (int i = 0; i < 4; i++)
        v[i] = *reinterpret_cast<const float4*>(h + (size_t)s[i] * ldH + lane * 4);
    #pragma unroll
    for (int i = 0; i < 4; i++)
        if (e0 + i < E)
            red_add_v4(agg + (size_t)d[i] * H + lane * 4, v[i]);
}

// ---------------- fused GIN MLP (layers 1,2), f32x2 packed ----------------
// C = relu(relu((A1+A2)@B1+b1)@B2+b2)
// smem: z_s[128*LDP] | As[16*LDP] | Bs[16*LDP]
__global__ void __launch_bounds__(256, 2)
fused_mlp_kernel(const float* __restrict__ A1, int ldA,
                 const float* __restrict__ A2,
                 const float* __restrict__ B1, const float* __restrict__ b1,
                 const float* __restrict__ B2, const float* __restrict__ b2,
                 float* __restrict__ C, int ldC, int N)
{
    extern __shared__ float sm[];
    float* z_s = sm;                      // 128 x LDP
    float* As  = sm + 128 * LDP;          // 16 x LDP (k-major)
    float* Bs  = As + 16 * LDP;           // 16 x LDP

    int tid = threadIdx.x;
    int tx = tid & 15, ty = tid >> 4;
    int m0 = blockIdx.x * 128;

    ull acc[8][4];
    #pragma unroll
    for (int i = 0; i < 8; i++)
        #pragma unroll
        for (int j = 0; j < 4; j++) acc[i][j] = 0ULL;

    // ---- phase 1: z = relu((A1+A2) @ B1 + b1) ----
    for (int kt = 0; kt < H; kt += 16) {
        #pragma unroll
        for (int u = 0; u < 2; u++) {
            int i = tid + u * 256;
            int row = i >> 2;
            int c4 = (i & 3) * 4;
            float4 v = make_float4(0.f, 0.f, 0.f, 0.f);
            int gr = m0 + row;
            if (gr < N) {
                v = *reinterpret_cast<const float4*>(A1 + (size_t)gr * ldA + kt + c4);
                float4 w = *reinterpret_cast<const float4*>(A2 + (size_t)gr * H + kt + c4);
                v.x += w.x; v.y += w.y; v.z += w.z; v.w += w.w;
            }
            As[(c4 + 0) * LDP + row] = v.x;
            As[(c4 + 1) * LDP + row] = v.y;
            As[(c4 + 2) * LDP + row] = v.z;
            As[(c4 + 3) * LDP + row] = v.w;
        }
        #pragma unroll
        for (int u = 0; u < 2; u++) {
            int i = tid + u * 256;
            int kr = i >> 5;
            int c4 = (i & 31) * 4;
            *reinterpret_cast<float4*>(&Bs[kr * LDP + c4]) =
                *reinterpret_cast<const float4*>(B1 + (size_t)(kt + kr) * H + c4);
        }
        __syncthreads();
        #pragma unroll
        for (int k = 0; k < 16; k++) {
            float4 a0 = *reinterpret_cast<const float4*>(&As[k * LDP + ty * 8]);
            float4 a1 = *reinterpret_cast<const float4*>(&As[k * LDP + ty * 8 + 4]);
            ulonglong2 bp0 = *reinterpret_cast<const ulonglong2*>(&Bs[k * LDP + tx * 8]);
            ulonglong2 bp1 = *reinterpret_cast<const ulonglong2*>(&Bs[k * LDP + tx * 8 + 4]);
            ull bb[4] = {bp0.x, bp0.y, bp1.x, bp1.y};
            float av[8] = {a0.x, a0.y, a0.z, a0.w, a1.x, a1.y, a1.z, a1.w};
            ull ad[8];
            #pragma unroll
            for (int i = 0; i < 8; i++) ad[i] = pkdup(av[i]);
            #pragma unroll
            for (int i = 0; i < 8; i++)
                #pragma unroll
                for (int j = 0; j < 4; j++) ffma2(acc[i][j], ad[i], bb[j]);
        }
        __syncthreads();
    }

    // epilogue 1: bias + relu -> z_s
    #pragma unroll
    for (int i = 0; i < 8; i++) {
        int r = ty * 8 + i;
        #pragma unroll
        for (int hlf = 0; hlf < 2; hlf++) {
            int j0 = tx * 8 + hlf * 4;
            float2 p0 = unpk(acc[i][hlf * 2 + 0]);
            float2 p1 = unpk(acc[i][hlf * 2 + 1]);
            float4 o;
            o.x = fmaxf(p0.x + b1[j0 + 0], 0.f);
            o.y = fmaxf(p0.y + b1[j0 + 1], 0.f);
            o.z = fmaxf(p1.x + b1[j0 + 2], 0.f);
            o.w = fmaxf(p1.y + b1[j0 + 3], 0.f);
            *reinterpret_cast<float4*>(&z_s[r * LDP + j0]) = o;
        }
    }

    // ---- phase 2: C = relu(z @ B2 + b2) ----
    ull acc2[8][4];
    #pragma unroll
    for (int i = 0; i < 8; i++)
        #pragma unroll
        for (int j = 0; j < 4; j++) acc2[i][j] = 0ULL;

    for (int kt = 0; kt < H; kt += 16) {
        #pragma unroll
        for (int u = 0; u < 2; u++) {
            int i = tid + u * 256;
            int kr = i >> 5;
            int c4 = (i & 31) * 4;
            *reinterpret_cast<float4*>(&Bs[kr * LDP + c4]) =
                *reinterpret_cast<const float4*>(B2 + (size_t)(kt + kr) * H + c4);
        }
        __syncthreads();
        #pragma unroll
        for (int kc = 0; kc < 16; kc += 4) {
            float4 rav[8];
            #pragma unroll
            for (int i = 0; i < 8; i++)
                rav[i] = *reinterpret_cast<const float4*>(&z_s[(ty * 8 + i) * LDP + kt + kc]);
            #pragma unroll
            for (int k4 = 0; k4 < 4; k4++) {
                int kr = kc + k4;
                ulonglong2 bp0 = *reinterpret_cast<const ulonglong2*>(&Bs[kr * LDP + tx * 8]);
                ulonglong2 bp1 = *reinterpret_cast<const ulonglong2*>(&Bs[kr * LDP + tx * 8 + 4]);
                ull bb[4] = {bp0.x, bp0.y, bp1.x, bp1.y};
                ull ad[8];
                #pragma unroll
                for (int i = 0; i < 8; i++) ad[i] = pkdup(f4c(rav[i], k4));
                #pragma unroll
                for (int i = 0; i < 8; i++)
                    #pragma unroll
                    for (int j = 0; j < 4; j++) ffma2(acc2[i][j], ad[i], bb[j]);
            }
        }
        __syncthreads();
    }

    // epilogue 2: bias + relu -> C
    #pragma unroll
    for (int i = 0; i < 8; i++) {
        int gr = m0 + ty * 8 + i;
        if (gr < N) {
            #pragma unroll
            for (int hlf = 0; hlf < 2; hlf++) {
                int j0 = tx * 8 + hlf * 4;
                float2 p0 = unpk(acc2[i][hlf * 2 + 0]);
                float2 p1 = unpk(acc2[i][hlf * 2 + 1]);
                float4 o;
                o.x = fmaxf(p0.x + b2[j0 + 0], 0.f);
                o.y = fmaxf(p0.y + b2[j0 + 1], 0.f);
                o.z = fmaxf(p1.x + b2[j0 + 2], 0.f);
                o.w = fmaxf(p1.y + b2[j0 + 3], 0.f);
                *reinterpret_cast<float4*>(C + (size_t)gr * ldC + j0) = o;
            }
        }
    }
}

// ---------------- fused layer-0 MLP: K1 = 7, f32x2 packed ----------------
// smem: z_s[128*LDP] | in_s[128*8] | Bs[16*LDP]
__global__ void __launch_bounds__(256, 2)
fused_l0_kernel(const float* __restrict__ x,
                const float* __restrict__ agg7,
                const float* __restrict__ B1, const float* __restrict__ b1,
                const float* __restrict__ B2, const float* __restrict__ b2,
                float* __restrict__ C, int ldC, int N)
{
    extern __shared__ float sm[];
    float* z_s  = sm;                     // 128 x LDP
    float* in_s = sm + 128 * LDP;         // 128 x 8
    float* Bs   = in_s + 1024;            // 16 x LDP

    int tid = threadIdx.x;
    int tx = tid & 15, ty = tid >> 4;
    int m0 = blockIdx.x * 128;

    for (int i = tid; i < 128 * IN_FEAT; i += 256) {
        int r = i / IN_FEAT, k = i % IN_FEAT;
        int gr = m0 + r;
        in_s[r * 8 + k] = (gr < N)
            ? x[(size_t)gr * IN_FEAT + k] + agg7[(size_t)gr * 8 + k] : 0.f;
    }
    for (int i = tid; i < IN_FEAT * H; i += 256) {
        int kr = i >> 7, c = i & 127;
        Bs[kr * LDP + c] = B1[i];
    }
    __syncthreads();

    // phase 1: z = relu(in @ B1 + b1)
    ull acc[8][4];
    #pragma unroll
    for (int i = 0; i < 8; i++)
        #pragma unroll
        for (int j = 0; j < 4; j++) acc[i][j] = 0ULL;

    #pragma unroll
    for (int k = 0; k < IN_FEAT; k++) {
        ulonglong2 bp0 = *reinterpret_cast<const ulonglong2*>(&Bs[k * LDP + tx * 8]);
        ulonglong2 bp1 = *reinterpret_cast<const ulonglong2*>(&Bs[k * LDP + tx * 8 + 4]);
        ull bb[4] = {bp0.x, bp0.y, bp1.x, bp1.y};
        ull ad[8];
        #pragma unroll
        for (int i = 0; i < 8; i++) ad[i] = pkdup(in_s[(ty * 8 + i) * 8 + k]);
        #pragma unroll
        for (int i = 0; i < 8; i++)
            #pragma unroll
            for (int j = 0; j < 4; j++) ffma2(acc[i][j], ad[i], bb[j]);
    }

    #pragma unroll
    for (int i = 0; i < 8; i++) {
        int r = ty * 8 + i;
        #pragma unroll
        for (int hlf = 0; hlf < 2; hlf++) {
            int j0 = tx * 8 + hlf * 4;
            float2 p0 = unpk(acc[i][hlf * 2 + 0]);
            float2 p1 = unpk(acc[i][hlf * 2 + 1]);
            float4 o;
            o.x = fmaxf(p0.x + b1[j0 + 0], 0.f);
            o.y = fmaxf(p0.y + b1[j0 + 1], 0.f);
            o.z = fmaxf(p1.x + b1[j0 + 2], 0.f);
            o.w = fmaxf(p1.y + b1[j0 + 3], 0.f);
            *reinterpret_cast<float4*>(&z_s[r * LDP + j0]) = o;
        }
    }
    __syncthreads();   // B1 reads done before Bs overwrite

    // phase 2: C = relu(z @ B2 + b2)
    ull acc2[8][4];
    #pragma unroll
    for (int i = 0; i < 8; i++)
        #pragma unroll
        for (int j = 0; j < 4; j++) acc2[i][j] = 0ULL;

    for (int kt = 0; kt < H; kt += 16) {
        #pragma unroll
        for (int u = 0; u < 2; u++) {
            int i = tid + u * 256;
            int kr = i >> 5;
            int c4 = (i & 31) * 4;
            *reinterpret_cast<float4*>(&Bs[kr * LDP + c4]) =
                *reinterpret_cast<const float4*>(B2 + (size_t)(kt + kr) * H + c4);
        }
        __syncthreads();
        #pragma unroll
        for (int kc = 0; kc < 16; kc += 4) {
            float4 rav[8];
            #pragma unroll
            for (int i = 0; i < 8; i++)
                rav[i] = *reinterpret_cast<const float4*>(&z_s[(ty * 8 + i) * LDP + kt + kc]);
            #pragma unroll
            for (int k4 = 0; k4 < 4; k4++) {
                int kr = kc + k4;
                ulonglong2 bp0 = *reinterpret_cast<const ulonglong2*>(&Bs[kr * LDP + tx * 8]);
                ulonglong2 bp1 = *reinterpret_cast<const ulonglong2*>(&Bs[kr * LDP + tx * 8 + 4]);
                ull bb[4] = {bp0.x, bp0.y, bp1.x, bp1.y};
                ull ad[8];
                #pragma unroll
                for (int i = 0; i < 8; i++) ad[i] = pkdup(f4c(rav[i], k4));
                #pragma unroll
                for (int i = 0; i < 8; i++)
                    #pragma unroll
                    for (int j = 0; j < 4; j++) ffma2(acc2[i][j], ad[i], bb[j]);
            }
        }
        __syncthreads();
    }

    #pragma unroll
    for (int i = 0; i < 8; i++) {
        int gr = m0 + ty * 8 + i;
        if (gr < N) {
            #pragma unroll
            for (int hlf = 0; hlf < 2; hlf++) {
                int j0 = tx * 8 + hlf * 4;
                float2 p0 = unpk(acc2[i][hlf * 2 + 0]);
                float2 p1 = unpk(acc2[i][hlf * 2 + 1]);
                float4 o;
                o.x = fmaxf(p0.x + b2[j0 + 0], 0.f);
                o.y = fmaxf(p0.y + b2[j0 + 1], 0.f);
                o.z = fmaxf(p1.x + b2[j0 + 2], 0.f);
                o.w = fmaxf(p1.y + b2[j0 + 3], 0.f);
                *reinterpret_cast<float4*>(C + (size_t)gr * ldC + j0) = o;
            }
        }
    }
}

// ---------------- global add pool over batch ids ----------------
__global__ void pool_kernel(const float* __restrict__ cat,
                            const int* __restrict__ batch,
                            float* __restrict__ pool, int N)
{
    int t = blockIdx.x * blockDim.x + threadIdx.x;
    int total = N * 96;
    if (t >= total) return;
    int n = t / 96;
    int q = t % 96;
    int g = batch[n];
    float4 v = reinterpret_cast<const float4*>(cat)[(size_t)n * 96 + q];
    red_add_v4(pool + (size_t)g * 384 + q * 4, v);
}

// ---------------- classifier layer 1: 4 graphs/block, 384 -> 256 + BN + relu --
__global__ void clf1_kernel(const float* __restrict__ pool,
                            const float* __restrict__ w,
                            const float* __restrict__ b,
                            const float* __restrict__ gamma,
                            const float* __restrict__ beta,
                            const float* __restrict__ mean,
                            const float* __restrict__ var,
                            float* __restrict__ hid)
{
    __shared__ float sp[4 * 384];
    int g0 = blockIdx.x * 4;
    int j = threadIdx.x;                 // 256
    for (int i = j; i < 4 * 384; i += 256)
        sp[i] = pool[(size_t)g0 * 384 + i];
    __syncthreads();

    float acc[4];
    float bj = b[j];
    #pragma unroll
    for (int g = 0; g < 4; g++) acc[g] = bj;

    #pragma unroll 4
    for (int k = 0; k < 384; k++) {
        float wv = __ldg(w + (size_t)k * 256 + j);
        #pragma unroll
        for (int g = 0; g < 4; g++) acc[g] += sp[g * 384 + k] * wv;
    }

    float scale = rsqrtf(var[j] + BN_EPS) * gamma[j];
    float shift = beta[j] - mean[j] * scale;
    #pragma unroll
    for (int g = 0; g < 4; g++)
        hid[(size_t)(g0 + g) * 256 + j] = fmaxf(acc[g] * scale + shift, 0.f);
}

// ---------------- classifier layer 2: 256 -> 2 ----------------
__global__ void clf2_kernel(const float* __restrict__ hid,
                            const float* __restrict__ w,
                            const float* __restrict__ b,
                            float* __restrict__ out)
{
    int t = blockIdx.x * blockDim.x + threadIdx.x;
    if (t >= NUM_GRAPHS * 2) return;
    int g = t >> 1, j = t & 1;
    float acc = b[j];
    const float* hr = hid + (size_t)g * 256;
    #pragma unroll 8
    for (int k = 0; k < 256; k++) acc += hr[k] * __ldg(w + k * 2 + j);
    out[t] = acc;
}

// ---------------- launch ----------------
extern "C" void kernel_launch(void* const* d_in, const int* in_sizes, int n_in,
                              void* d_out, int out_size)
{
    const float* x      = (const float*)d_in[0];
    const int*   ei     = (const int*)d_in[1];
    const int*   batch  = (const int*)d_in[2];
    const float* w1[3], *b1[3], *w2[3], *b2[3];
    for (int l = 0; l < 3; l++) {
        w1[l] = (const float*)d_in[3 + 4 * l + 0];
        b1[l] = (const float*)d_in[3 + 4 * l + 1];
        w2[l] = (const float*)d_in[3 + 4 * l + 2];
        b2[l] = (const float*)d_in[3 + 4 * l + 3];
    }
    const float* clf_w1 = (const float*)d_in[15];
    const float* clf_b1 = (const float*)d_in[16];
    const float* clf_w2 = (const float*)d_in[17];
    const float* clf_b2 = (const float*)d_in[18];
    const float* bn_g   = (const float*)d_in[19];
    const float* bn_b   = (const float*)d_in[20];
    const float* bn_m   = (const float*)d_in[21];
    const float* bn_v   = (const float*)d_in[22];
    float* out = (float*)d_out;

    const int N = in_sizes[0] / IN_FEAT;     // 100000
    const int E = in_sizes[1] / 2;           // 1600000

    float *d_agg, *d_cat, *d_pool, *d_hid;
    cudaGetSymbolAddress((void**)&d_agg, g_agg);
    cudaGetSymbolAddress((void**)&d_cat, g_cat);
    cudaGetSymbolAddress((void**)&d_pool, g_pool);
    cudaGetSymbolAddress((void**)&d_hid, g_hid);

    const int* src = ei;
    const int* dst = ei + E;

    const int gemm_blocks = (N + 127) / 128;
    const int SMEM_MLP = (128 * LDP + 16 * LDP + 16 * LDP) * 4;   // 84480
    const int SMEM_L0  = (128 * LDP + 1024 + 16 * LDP) * 4;       // 80128
    cudaFuncSetAttribute(fused_mlp_kernel, cudaFuncAttributeMaxDynamicSharedMemorySize, SMEM_MLP);
    cudaFuncSetAttribute(fused_l0_kernel,  cudaFuncAttributeMaxDynamicSharedMemorySize, SMEM_L0);

    // ---- layer 0 ----
    cudaMemsetAsync(d_agg, 0, (size_t)N * 8 * sizeof(float));
    scatter7_kernel<<<(E + 255) / 256, 256>>>(x, src, dst, d_agg, E);
    fused_l0_kernel<<<gemm_blocks, 256, SMEM_L0>>>(x, d_agg, w1[0], b1[0],
                                                   w2[0], b2[0], d_cat, 3 * H, N);

    // ---- layers 1, 2 ----
    for (int l = 1; l < 3; l++) {
        const float* h_prev = d_cat + (size_t)(l - 1) * H;  // row stride 384
        cudaMemsetAsync(d_agg, 0, (size_t)N * H * sizeof(float));
        int warps = (E + 3) / 4;
        scatter128_kernel<<<(warps * 32 + 255) / 256, 256>>>(h_prev, 3 * H, src, dst, d_agg, E);
        fused_mlp_kernel<<<gemm_blocks, 256, SMEM_MLP>>>(h_prev, 3 * H, d_agg,
                                                         w1[l], b1[l], w2[l], b2[l],
                                                         d_cat + (size_t)l * H, 3 * H, N);
    }

    // ---- global add pool ----
    cudaMemsetAsync(d_pool, 0, (size_t)NUM_GRAPHS * 384 * sizeof(float));
    pool_kernel<<<(N * 96 + 255) / 256, 256>>>(d_cat, batch, d_pool, N);

    // ---- classifier ----
    clf1_kernel<<<NUM_GRAPHS / 4, 256>>>(d_pool, clf_w1, clf_b1, bn_g, bn_b, bn_m, bn_v, d_hid);
    clf2_kernel<<<(NUM_GRAPHS * 2 + 255) / 256, 256>>>(d_hid, clf_w2, clf_b2, out);
}

// round 9
// speedup vs baseline: 1.1586x; 1.0927x over previous
#include <cuda_runtime.h>
#include <cuda_bf16.h>
#include <cstdint>

// ---------------- problem constants ----------------
#define N_NODES   100000
#define N_EDGES   1600000
#define NUM_GRAPHS 1024
#define IN_FEAT   7
#define H         128
#define BN_EPS    1e-5f

#define LDP 132   // padded smem row stride (floats)

typedef unsigned long long ull;

// ---------------- scratch (device globals, no allocation) ----------------
__device__ __align__(256) float g_agg[(size_t)N_NODES * H];     // also N x 8 for layer 0
__device__ __align__(256) float g_cat[(size_t)N_NODES * 3 * H];
__device__ __align__(256) float g_pool[(size_t)NUM_GRAPHS * 3 * H];
__device__ __align__(256) float g_hid[(size_t)NUM_GRAPHS * 2 * H];

// ---------------- f32x2 packed-math helpers ----------------
__device__ __forceinline__ void ffma2(ull& d, ull a, ull b) {
    asm("fma.rn.f32x2 %0, %1, %2, %0;" : "+l"(d) : "l"(a), "l"(b));
}
__device__ __forceinline__ ull pkdup(float a) {
    ull r; asm("mov.b64 %0, {%1, %1};" : "=l"(r) : "f"(a)); return r;
}
__device__ __forceinline__ float2 unpk(ull v) {
    float2 r; asm("mov.b64 {%0, %1}, %2;" : "=f"(r.x), "=f"(r.y) : "l"(v)); return r;
}
__device__ __forceinline__ void red_add_v4(float* addr, float4 v) {
    asm volatile("red.global.add.v4.f32 [%0], {%1, %2, %3, %4};"
                 :: "l"(addr), "f"(v.x), "f"(v.y), "f"(v.z), "f"(v.w)
                 : "memory");
}
__device__ __forceinline__ float f4c(const float4& v, int k) {
    return (k == 0) ? v.x : (k == 1) ? v.y : (k == 2) ? v.z : v.w;
}

// ---------------- layer 0: scatter of 7-dim raw features ----------------
__global__ void scatter7_kernel(const float* __restrict__ x,
                                const int* __restrict__ src,
                                const int* __restrict__ dst,
                                float* __restrict__ agg, int E)
{
    int e = blockIdx.x * blockDim.x + threadIdx.x;
    if (e >= E) return;
    int s = src[e];
    int d = dst[e];
    const float* xr = x + (size_t)s * IN_FEAT;
    float* ar = agg + (size_t)d * 8;
    #pragma unroll
    for (int k = 0; k < IN_FEAT; k++) atomicAdd(ar + k, xr[k]);
}

// ---------------- scatter for H=128 features: 4 edges per warp ----------------
__global__ void scatter128_kernel(const float* __restrict__ h, int ldH,
                                  const int* __restrict__ src,
                                  const int* __restrict__ dst,
                                  float* __restrict__ agg, int E)
{
    int warp = (blockIdx.x * blockDim.x + threadIdx.x) >> 5;
    int lane = threadIdx.x & 31;
    int e0 = warp * 4;
    if (e0 >= E) return;

    int s[4], d[4];
    #pragma unroll
    for (int i = 0; i < 4; i++) {
        int e = (e0 + i < E) ? (e0 + i) : (E - 1);
        s[i] = __ldg(src + e);
        d[i] = __ldg(dst + e);
    }
    float4 v[4];
    #pragma unroll
    for (int i = 0; i < 4; i++)
        v[i] = *reinterpret_cast<const float4*>(h + (size_t)s[i] * ldH + lane * 4);
    #pragma unroll
    for (int i = 0; i < 4; i++)
        if (e0 + i < E)
            red_add_v4(agg + (size_t)d[i] * H + lane * 4, v[i]);
}

// ---------------- fused GIN MLP (layers 1,2), f32x2 + conflict-free mapping ----
// Thread (tx,ty) owns rows ty*8..+7, cols {tx*4..+3, 64+tx*4..+3}.
// acc[i][0..1] = cols tx*4+{0,1},{2,3};  acc[i][2..3] = cols 64+tx*4+{0,1},{2,3}.
// smem: z_s[128*LDP] | As[16*LDP] | Bs[16*LDP]
__global__ void __launch_bounds__(256, 2)
fused_mlp_kernel(const float* __restrict__ A1, int ldA,
                 const float* __restrict__ A2,
                 const float* __restrict__ B1, const float* __restrict__ b1,
                 const float* __restrict__ B2, const float* __restrict__ b2,
                 float* __restrict__ C, int ldC, int N)
{
    extern __shared__ float sm[];
    float* z_s = sm;                      // 128 x LDP
    float* As  = sm + 128 * LDP;          // 16 x LDP (k-major)
    float* Bs  = As + 16 * LDP;           // 16 x LDP

    int tid = threadIdx.x;
    int tx = tid & 15, ty = tid >> 4;
    int m0 = blockIdx.x * 128;

    ull acc[8][4];
    #pragma unroll
    for (int i = 0; i < 8; i++)
        #pragma unroll
        for (int j = 0; j < 4; j++) acc[i][j] = 0ULL;

    // ---- phase 1: z = relu((A1+A2) @ B1 + b1) ----
    for (int kt = 0; kt < H; kt += 16) {
        #pragma unroll
        for (int u = 0; u < 2; u++) {
            int i = tid + u * 256;
            int row = i >> 2;
            int c4 = (i & 3) * 4;
            float4 v = make_float4(0.f, 0.f, 0.f, 0.f);
            int gr = m0 + row;
            if (gr < N) {
                v = *reinterpret_cast<const float4*>(A1 + (size_t)gr * ldA + kt + c4);
                float4 w = *reinterpret_cast<const float4*>(A2 + (size_t)gr * H + kt + c4);
                v.x += w.x; v.y += w.y; v.z += w.z; v.w += w.w;
            }
            As[(c4 + 0) * LDP + row] = v.x;
            As[(c4 + 1) * LDP + row] = v.y;
            As[(c4 + 2) * LDP + row] = v.z;
            As[(c4 + 3) * LDP + row] = v.w;
        }
        #pragma unroll
        for (int u = 0; u < 2; u++) {
            int i = tid + u * 256;
            int kr = i >> 5;
            int c4 = (i & 31) * 4;
            *reinterpret_cast<float4*>(&Bs[kr * LDP + c4]) =
                *reinterpret_cast<const float4*>(B1 + (size_t)(kt + kr) * H + c4);
        }
        __syncthreads();
        #pragma unroll
        for (int k = 0; k < 16; k++) {
            float4 a0 = *reinterpret_cast<const float4*>(&As[k * LDP + ty * 8]);
            float4 a1 = *reinterpret_cast<const float4*>(&As[k * LDP + ty * 8 + 4]);
            // conflict-free B: contiguous float4 per lane at tx*4 and 64+tx*4
            ulonglong2 bp0 = *reinterpret_cast<const ulonglong2*>(&Bs[k * LDP + tx * 4]);
            ulonglong2 bp1 = *reinterpret_cast<const ulonglong2*>(&Bs[k * LDP + 64 + tx * 4]);
            ull bb[4] = {bp0.x, bp0.y, bp1.x, bp1.y};
            float av[8] = {a0.x, a0.y, a0.z, a0.w, a1.x, a1.y, a1.z, a1.w};
            ull ad[8];
            #pragma unroll
            for (int i = 0; i < 8; i++) ad[i] = pkdup(av[i]);
            #pragma unroll
            for (int i = 0; i < 8; i++)
                #pragma unroll
                for (int j = 0; j < 4; j++) ffma2(acc[i][j], ad[i], bb[j]);
        }
        __syncthreads();
    }

    // epilogue 1: bias + relu -> z_s (two float4 stores at tx*4, 64+tx*4)
    #pragma unroll
    for (int i = 0; i < 8; i++) {
        int r = ty * 8 + i;
        #pragma unroll
        for (int hlf = 0; hlf < 2; hlf++) {
            int j0 = hlf * 64 + tx * 4;
            float2 p0 = unpk(acc[i][hlf * 2 + 0]);
            float2 p1 = unpk(acc[i][hlf * 2 + 1]);
            float4 o;
            o.x = fmaxf(p0.x + b1[j0 + 0], 0.f);
            o.y = fmaxf(p0.y + b1[j0 + 1], 0.f);
            o.z = fmaxf(p1.x + b1[j0 + 2], 0.f);
            o.w = fmaxf(p1.y + b1[j0 + 3], 0.f);
            *reinterpret_cast<float4*>(&z_s[r * LDP + j0]) = o;
        }
    }

    // ---- phase 2: C = relu(z @ B2 + b2) ----
    ull acc2[8][4];
    #pragma unroll
    for (int i = 0; i < 8; i++)
        #pragma unroll
        for (int j = 0; j < 4; j++) acc2[i][j] = 0ULL;

    for (int kt = 0; kt < H; kt += 16) {
        #pragma unroll
        for (int u = 0; u < 2; u++) {
            int i = tid + u * 256;
            int kr = i >> 5;
            int c4 = (i & 31) * 4;
            *reinterpret_cast<float4*>(&Bs[kr * LDP + c4]) =
                *reinterpret_cast<const float4*>(B2 + (size_t)(kt + kr) * H + c4);
        }
        __syncthreads();
        #pragma unroll
        for (int kc = 0; kc < 16; kc += 4) {
            float4 rav[8];
            #pragma unroll
            for (int i = 0; i < 8; i++)
                rav[i] = *reinterpret_cast<const float4*>(&z_s[(ty * 8 + i) * LDP + kt + kc]);
            #pragma unroll
            for (int k4 = 0; k4 < 4; k4++) {
                int kr = kc + k4;
                ulonglong2 bp0 = *reinterpret_cast<const ulonglong2*>(&Bs[kr * LDP + tx * 4]);
                ulonglong2 bp1 = *reinterpret_cast<const ulonglong2*>(&Bs[kr * LDP + 64 + tx * 4]);
                ull bb[4] = {bp0.x, bp0.y, bp1.x, bp1.y};
                ull ad[8];
                #pragma unroll
                for (int i = 0; i < 8; i++) ad[i] = pkdup(f4c(rav[i], k4));
                #pragma unroll
                for (int i = 0; i < 8; i++)
                    #pragma unroll
                    for (int j = 0; j < 4; j++) ffma2(acc2[i][j], ad[i], bb[j]);
            }
        }
        __syncthreads();
    }

    // epilogue 2: bias + relu -> C
    #pragma unroll
    for (int i = 0; i < 8; i++) {
        int gr = m0 + ty * 8 + i;
        if (gr < N) {
            #pragma unroll
            for (int hlf = 0; hlf < 2; hlf++) {
                int j0 = hlf * 64 + tx * 4;
                float2 p0 = unpk(acc2[i][hlf * 2 + 0]);
                float2 p1 = unpk(acc2[i][hlf * 2 + 1]);
                float4 o;
                o.x = fmaxf(p0.x + b2[j0 + 0], 0.f);
                o.y = fmaxf(p0.y + b2[j0 + 1], 0.f);
                o.z = fmaxf(p1.x + b2[j0 + 2], 0.f);
                o.w = fmaxf(p1.y + b2[j0 + 3], 0.f);
                *reinterpret_cast<float4*>(C + (size_t)gr * ldC + j0) = o;
            }
        }
    }
}

// ---------------- fused layer-0 MLP: K1 = 7, conflict-free mapping -----------
// smem: z_s[128*LDP] | in_s[128*8] | Bs[16*LDP]
__global__ void __launch_bounds__(256, 2)
fused_l0_kernel(const float* __restrict__ x,
                const float* __restrict__ agg7,
                const float* __restrict__ B1, const float* __restrict__ b1,
                const float* __restrict__ B2, const float* __restrict__ b2,
                float* __restrict__ C, int ldC, int N)
{
    extern __shared__ float sm[];
    float* z_s  = sm;                     // 128 x LDP
    float* in_s = sm + 128 * LDP;         // 128 x 8
    float* Bs   = in_s + 1024;            // 16 x LDP

    int tid = threadIdx.x;
    int tx = tid & 15, ty = tid >> 4;
    int m0 = blockIdx.x * 128;

    for (int i = tid; i < 128 * IN_FEAT; i += 256) {
        int r = i / IN_FEAT, k = i % IN_FEAT;
        int gr = m0 + r;
        in_s[r * 8 + k] = (gr < N)
            ? x[(size_t)gr * IN_FEAT + k] + agg7[(size_t)gr * 8 + k] : 0.f;
    }
    for (int i = tid; i < IN_FEAT * H; i += 256) {
        int kr = i >> 7, c = i & 127;
        Bs[kr * LDP + c] = B1[i];
    }
    __syncthreads();

    // phase 1: z = relu(in @ B1 + b1)
    ull acc[8][4];
    #pragma unroll
    for (int i = 0; i < 8; i++)
        #pragma unroll
        for (int j = 0; j < 4; j++) acc[i][j] = 0ULL;

    #pragma unroll
    for (int k = 0; k < IN_FEAT; k++) {
        ulonglong2 bp0 = *reinterpret_cast<const ulonglong2*>(&Bs[k * LDP + tx * 4]);
        ulonglong2 bp1 = *reinterpret_cast<const ulonglong2*>(&Bs[k * LDP + 64 + tx * 4]);
        ull bb[4] = {bp0.x, bp0.y, bp1.x, bp1.y};
        ull ad[8];
        #pragma unroll
        for (int i = 0; i < 8; i++) ad[i] = pkdup(in_s[(ty * 8 + i) * 8 + k]);
        #pragma unroll
        for (int i = 0; i < 8; i++)
            #pragma unroll
            for (int j = 0; j < 4; j++) ffma2(acc[i][j], ad[i], bb[j]);
    }

    #pragma unroll
    for (int i = 0; i < 8; i++) {
        int r = ty * 8 + i;
        #pragma unroll
        for (int hlf = 0; hlf < 2; hlf++) {
            int j0 = hlf * 64 + tx * 4;
            float2 p0 = unpk(acc[i][hlf * 2 + 0]);
            float2 p1 = unpk(acc[i][hlf * 2 + 1]);
            float4 o;
            o.x = fmaxf(p0.x + b1[j0 + 0], 0.f);
            o.y = fmaxf(p0.y + b1[j0 + 1], 0.f);
            o.z = fmaxf(p1.x + b1[j0 + 2], 0.f);
            o.w = fmaxf(p1.y + b1[j0 + 3], 0.f);
            *reinterpret_cast<float4*>(&z_s[r * LDP + j0]) = o;
        }
    }
    __syncthreads();   // B1 reads done before Bs overwrite

    // phase 2: C = relu(z @ B2 + b2)
    ull acc2[8][4];
    #pragma unroll
    for (int i = 0; i < 8; i++)
        #pragma unroll
        for (int j = 0; j < 4; j++) acc2[i][j] = 0ULL;

    for (int kt = 0; kt < H; kt += 16) {
        #pragma unroll
        for (int u = 0; u < 2; u++) {
            int i = tid + u * 256;
            int kr = i >> 5;
            int c4 = (i & 31) * 4;
            *reinterpret_cast<float4*>(&Bs[kr * LDP + c4]) =
                *reinterpret_cast<const float4*>(B2 + (size_t)(kt + kr) * H + c4);
        }
        __syncthreads();
        #pragma unroll
        for (int kc = 0; kc < 16; kc += 4) {
            float4 rav[8];
            #pragma unroll
            for (int i = 0; i < 8; i++)
                rav[i] = *reinterpret_cast<const float4*>(&z_s[(ty * 8 + i) * LDP + kt + kc]);
            #pragma unroll
            for (int k4 = 0; k4 < 4; k4++) {
                int kr = kc + k4;
                ulonglong2 bp0 = *reinterpret_cast<const ulonglong2*>(&Bs[kr * LDP + tx * 4]);
                ulonglong2 bp1 = *reinterpret_cast<const ulonglong2*>(&Bs[kr * LDP + 64 + tx * 4]);
                ull bb[4] = {bp0.x, bp0.y, bp1.x, bp1.y};
                ull ad[8];
                #pragma unroll
                for (int i = 0; i < 8; i++) ad[i] = pkdup(f4c(rav[i], k4));
                #pragma unroll
                for (int i = 0; i < 8; i++)
                    #pragma unroll
                    for (int j = 0; j < 4; j++) ffma2(acc2[i][j], ad[i], bb[j]);
            }
        }
        __syncthreads();
    }

    #pragma unroll
    for (int i = 0; i < 8; i++) {
        int gr = m0 + ty * 8 + i;
        if (gr < N) {
            #pragma unroll
            for (int hlf = 0; hlf < 2; hlf++) {
                int j0 = hlf * 64 + tx * 4;
                float2 p0 = unpk(acc2[i][hlf * 2 + 0]);
                float2 p1 = unpk(acc2[i][hlf * 2 + 1]);
                float4 o;
                o.x = fmaxf(p0.x + b2[j0 + 0], 0.f);
                o.y = fmaxf(p0.y + b2[j0 + 1], 0.f);
                o.z = fmaxf(p1.x + b2[j0 + 2], 0.f);
                o.w = fmaxf(p1.y + b2[j0 + 3], 0.f);
                *reinterpret_cast<float4*>(C + (size_t)gr * ldC + j0) = o;
            }
        }
    }
}

// ---------------- global add pool over batch ids ----------------
__global__ void pool_kernel(const float* __restrict__ cat,
                            const int* __restrict__ batch,
                            float* __restrict__ pool, int N)
{
    int t = blockIdx.x * blockDim.x + threadIdx.x;
    int total = N * 96;
    if (t >= total) return;
    int n = t / 96;
    int q = t % 96;
    int g = batch[n];
    float4 v = reinterpret_cast<const float4*>(cat)[(size_t)n * 96 + q];
    red_add_v4(pool + (size_t)g * 384 + q * 4, v);
}

// ---------------- classifier layer 1 (R4 proven): 384 -> 256 + BN + relu ------
__global__ void clf1_kernel(const float* __restrict__ pool,
                            const float* __restrict__ w,
                            const float* __restrict__ b,
                            const float* __restrict__ gamma,
                            const float* __restrict__ beta,
                            const float* __restrict__ mean,
                            const float* __restrict__ var,
                            float* __restrict__ hid)
{
    __shared__ float sp[384];
    int g = blockIdx.x;
    int j = threadIdx.x;                 // 256
    for (int i = j; i < 384; i += 256) sp[i] = pool[(size_t)g * 384 + i];
    __syncthreads();
    float acc = b[j];
    #pragma unroll 8
    for (int k = 0; k < 384; k++) acc += sp[k] * __ldg(w + (size_t)k * 256 + j);
    acc = (acc - mean[j]) * rsqrtf(var[j] + BN_EPS) * gamma[j] + beta[j];
    hid[(size_t)g * 256 + j] = fmaxf(acc, 0.f);
}

// ---------------- classifier layer 2: 256 -> 2 ----------------
__global__ void clf2_kernel(const float* __restrict__ hid,
                            const float* __restrict__ w,
                            const float* __restrict__ b,
                            float* __restrict__ out)
{
    int t = blockIdx.x * blockDim.x + threadIdx.x;
    if (t >= NUM_GRAPHS * 2) return;
    int g = t >> 1, j = t & 1;
    float acc = b[j];
    const float* hr = hid + (size_t)g * 256;
    #pragma unroll 8
    for (int k = 0; k < 256; k++) acc += hr[k] * __ldg(w + k * 2 + j);
    out[t] = acc;
}

// ---------------- launch ----------------
extern "C" void kernel_launch(void* const* d_in, const int* in_sizes, int n_in,
                              void* d_out, int out_size)
{
    const float* x      = (const float*)d_in[0];
    const int*   ei     = (const int*)d_in[1];
    const int*   batch  = (const int*)d_in[2];
    const float* w1[3], *b1[3], *w2[3], *b2[3];
    for (int l = 0; l < 3; l++) {
        w1[l] = (const float*)d_in[3 + 4 * l + 0];
        b1[l] = (const float*)d_in[3 + 4 * l + 1];
        w2[l] = (const float*)d_in[3 + 4 * l + 2];
        b2[l] = (const float*)d_in[3 + 4 * l + 3];
    }
    const float* clf_w1 = (const float*)d_in[15];
    const float* clf_b1 = (const float*)d_in[16];
    const float* clf_w2 = (const float*)d_in[17];
    const float* clf_b2 = (const float*)d_in[18];
    const float* bn_g   = (const float*)d_in[19];
    const float* bn_b   = (const float*)d_in[20];
    const float* bn_m   = (const float*)d_in[21];
    const float* bn_v   = (const float*)d_in[22];
    float* out = (float*)d_out;

    const int N = in_sizes[0] / IN_FEAT;     // 100000
    const int E = in_sizes[1] / 2;           // 1600000

    float *d_agg, *d_cat, *d_pool, *d_hid;
    cudaGetSymbolAddress((void**)&d_agg, g_agg);
    cudaGetSymbolAddress((void**)&d_cat, g_cat);
    cudaGetSymbolAddress((void**)&d_pool, g_pool);
    cudaGetSymbolAddress((void**)&d_hid, g_hid);

    const int* src = ei;
    const int* dst = ei + E;

    const int gemm_blocks = (N + 127) / 128;
    const int SMEM_MLP = (128 * LDP + 16 * LDP + 16 * LDP) * 4;   // 84480
    const int SMEM_L0  = (128 * LDP + 1024 + 16 * LDP) * 4;       // 80128
    cudaFuncSetAttribute(fused_mlp_kernel, cudaFuncAttributeMaxDynamicSharedMemorySize, SMEM_MLP);
    cudaFuncSetAttribute(fused_l0_kernel,  cudaFuncAttributeMaxDynamicSharedMemorySize, SMEM_L0);

    // ---- layer 0 ----
    cudaMemsetAsync(d_agg, 0, (size_t)N * 8 * sizeof(float));
    scatter7_kernel<<<(E + 255) / 256, 256>>>(x, src, dst, d_agg, E);
    fused_l0_kernel<<<gemm_blocks, 256, SMEM_L0>>>(x, d_agg, w1[0], b1[0],
                                                   w2[0], b2[0], d_cat, 3 * H, N);

    // ---- layers 1, 2 ----
    for (int l = 1; l < 3; l++) {
        const float* h_prev = d_cat + (size_t)(l - 1) * H;  // row stride 384
        cudaMemsetAsync(d_agg, 0, (size_t)N * H * sizeof(float));
        int warps = (E + 3) / 4;
        scatter128_kernel<<<(warps * 32 + 255) / 256, 256>>>(h_prev, 3 * H, src, dst, d_agg, E);
        fused_mlp_kernel<<<gemm_blocks, 256, SMEM_MLP>>>(h_prev, 3 * H, d_agg,
                                                         w1[l], b1[l], w2[l], b2[l],
                                                         d_cat + (size_t)l * H, 3 * H, N);
    }

    // ---- global add pool ----
    cudaMemsetAsync(d_pool, 0, (size_t)NUM_GRAPHS * 384 * sizeof(float));
    pool_kernel<<<(N * 96 + 255) / 256, 256>>>(d_cat, batch, d_pool, N);

    // ---- classifier ----
    clf1_kernel<<<NUM_GRAPHS, 256>>>(d_pool, clf_w1, clf_b1, bn_g, bn_b, bn_m, bn_v, d_hid);
    clf2_kernel<<<(NUM_GRAPHS * 2 + 255) / 256, 256>>>(d_hid, clf_w2, clf_b2, out);
}